// round 7
// baseline (speedup 1.0000x reference)
#include <cuda_runtime.h>

// ---------------------------------------------------------------------------
// QNNClassifier fused single-kernel.
//
//   ev = (1, cos x0, sin x0)^T K (1, cos x1, sin x1)
//
// K (9 coefficients, fc_w/fc_b folded) depends only on q_params. Warp 0 of
// each block computes it: lane L = 4i+j computes A[i][j] by pushing basis
// columns e_i, e_j through the 2-layer circuit with factored per-wire 2x2
// complex ops (NO shuffles in the dependency chain -> ~300 cycle critical
// path, fully hidden under the block's front-batched DRAM loads).
// Main path: 4 samples/thread (proven shape).
// ---------------------------------------------------------------------------

struct Cx { float re, im; };
__device__ __forceinline__ Cx cmul(Cx a, Cx b) {
    return { a.re * b.re - a.im * b.im, a.re * b.im + a.im * b.re };
}
__device__ __forceinline__ Cx cmadd2(Cx a, Cx x, Cx b, Cx y) {
    // a*x + b*y
    return { a.re * x.re - a.im * x.im + b.re * y.re - b.im * y.im,
             a.re * x.im + a.im * x.re + b.re * y.im + b.im * y.re };
}

// Warp-collective (warp 0 only). Lanes 0-15 active for the matrix work.
__device__ __forceinline__ void warp_compute_K(const float* __restrict__ qp,
                                               const float* __restrict__ fc_w,
                                               const float* __restrict__ fc_b,
                                               float* sA, float* sK) {
    int L = threadIdx.x & 31;
    if (L < 16) {
        int i = L >> 2, j = L & 3;

        // Two basis columns propagated through the circuit.
        Cx vI[4], vJ[4];
        #pragma unroll
        for (int k = 0; k < 4; k++) {
            vI[k] = { (k == i) ? 1.f : 0.f, 0.f };
            vJ[k] = { (k == j) ? 1.f : 0.f, 0.f };
        }

        #pragma unroll
        for (int l = 0; l < 2; l++) {
            float ph0 = qp[l * 6 + 0], th0 = qp[l * 6 + 1], om0 = qp[l * 6 + 2];
            float ph1 = qp[l * 6 + 3], th1 = qp[l * 6 + 4], om1 = qp[l * 6 + 5];

            float s0, c0; __sincosf(0.5f * th0, &s0, &c0);
            float sp0, cp0, sm0, cm0;
            __sincosf(-0.5f * (ph0 + om0), &sp0, &cp0);   // ep0
            __sincosf( 0.5f * (ph0 - om0), &sm0, &cm0);   // em0
            Cx r0_00 = {  cp0 * c0,  sp0 * c0 };
            Cx r0_01 = { -cm0 * s0, -sm0 * s0 };
            Cx r0_10 = {  cm0 * s0, -sm0 * s0 };
            Cx r0_11 = {  cp0 * c0, -sp0 * c0 };

            float s1, c1; __sincosf(0.5f * th1, &s1, &c1);
            float sp1, cp1, sm1, cm1;
            __sincosf(-0.5f * (ph1 + om1), &sp1, &cp1);
            __sincosf( 0.5f * (ph1 - om1), &sm1, &cm1);
            Cx r1_00 = {  cp1 * c1,  sp1 * c1 };
            Cx r1_01 = { -cm1 * s1, -sm1 * s1 };
            Cx r1_10 = {  cm1 * s1, -sm1 * s1 };
            Cx r1_11 = {  cp1 * c1, -sp1 * c1 };

            // Apply kron(r0, r1) then the CNOT row permutation {0,2,3,1}
            // to both columns. Factored: r1 on wire1, r0 on wire0.
            #pragma unroll
            for (int col = 0; col < 2; col++) {
                Cx* v = col ? vJ : vI;
                Cx u0 = cmadd2(r1_00, v[0], r1_01, v[1]);
                Cx u1 = cmadd2(r1_10, v[0], r1_11, v[1]);
                Cx u2 = cmadd2(r1_00, v[2], r1_01, v[3]);
                Cx u3 = cmadd2(r1_10, v[2], r1_11, v[3]);
                Cx w0 = cmadd2(r0_00, u0, r0_01, u2);
                Cx w1 = cmadd2(r0_00, u1, r0_01, u3);
                Cx w2 = cmadd2(r0_10, u0, r0_11, u2);
                Cx w3 = cmadd2(r0_10, u1, r0_11, u3);
                // new[r] = w[perm[r]], perm = {0,2,3,1}
                v[0] = w0; v[1] = w2; v[2] = w3; v[3] = w1;
            }
        }

        // A[i][j] = Re( sum_k z_k conj(colI[k]) colJ[k] ), z = (1,1,-1,-1)
        float acc = (vI[0].re * vJ[0].re + vI[0].im * vJ[0].im)
                  + (vI[1].re * vJ[1].re + vI[1].im * vJ[1].im)
                  - (vI[2].re * vJ[2].re + vI[2].im * vJ[2].im)
                  - (vI[3].re * vJ[3].re + vI[3].im * vJ[3].im);
        sA[L] = acc;
    }
    __syncwarp();

    if (L == 0) {
        float w = fc_w[0];
        float A00 = w * sA[0],  A01 = w * sA[1],  A02 = w * sA[2],  A03 = w * sA[3];
        float A11 = w * sA[5],  A12 = w * sA[6],  A13 = w * sA[7];
        float A22 = w * sA[10], A23 = w * sA[11], A33 = w * sA[15];
        sK[0] = 0.25f * (A00 + A11 + A22 + A33) + fc_b[0];
        sK[1] = 0.25f * (A00 - A11 + A22 - A33);   // C1
        sK[2] = 0.50f * (A01 + A23);               // S1
        sK[3] = 0.25f * (A00 + A11 - A22 - A33);   // C0
        sK[4] = 0.25f * (A00 - A11 - A22 + A33);   // C0C1
        sK[5] = 0.50f * (A01 - A23);               // C0S1
        sK[6] = 0.50f * (A02 + A13);               // S0
        sK[7] = 0.50f * (A02 - A13);               // S0C1
        sK[8] = 0.50f * (A03 + A12);               // S0S1
    }
}

// 4 samples per thread: 2 input float4, 1 output float4.
__global__ void __launch_bounds__(256, 6)
qnn_fused_kernel(const float* __restrict__ qp,
                 const float* __restrict__ fc_w,
                 const float* __restrict__ fc_b,
                 const float4* __restrict__ x4,
                 float4* __restrict__ out4,
                 int nquad) {
    __shared__ float sA[16];
    __shared__ float sK[9];
    unsigned t = blockIdx.x * 256u + threadIdx.x;

    float4 xa, xb;
    if (t < (unsigned)nquad) {
        xa = __ldcs(&x4[2u * t + 0]);
        xb = __ldcs(&x4[2u * t + 1]);
    }

    if (threadIdx.x < 32) {
        warp_compute_K(qp, fc_w, fc_b, sA, sK);
    }
    __syncthreads();

    if (t >= (unsigned)nquad) return;

    float k00 = sK[0], k01 = sK[1], k02 = sK[2];
    float k10 = sK[3], k11 = sK[4], k12 = sK[5];
    float k20 = sK[6], k21 = sK[7], k22 = sK[8];

    float xs[8] = { xa.x, xa.y, xa.z, xa.w, xb.x, xb.y, xb.z, xb.w };

    float res[4];
    #pragma unroll
    for (int s = 0; s < 4; s++) {
        float C0, S0, C1, S1;
        __sincosf(xs[2 * s + 0], &S0, &C0);
        __sincosf(xs[2 * s + 1], &S1, &C1);
        float row0 = k00 + k01 * C1 + k02 * S1;
        float row1 = k10 + k11 * C1 + k12 * S1;
        float row2 = k20 + k21 * C1 + k22 * S1;
        res[s] = row0 + C0 * row1 + S0 * row2;
    }

    __stcs(&out4[t], make_float4(res[0], res[1], res[2], res[3]));
}

extern "C" void kernel_launch(void* const* d_in, const int* in_sizes, int n_in,
                              void* d_out, int out_size) {
    const float* x    = (const float*)d_in[0];   // [B, 2]
    const float* qp   = (const float*)d_in[1];   // [2, 2, 3]
    const float* fc_w = (const float*)d_in[2];   // [1, 1]
    const float* fc_b = (const float*)d_in[3];   // [1]

    int nquad = out_size / 4;                    // 4 samples per thread
    int threads = 256;
    int blocks = (nquad + threads - 1) / threads;   // 2048 for B=2M
    qnn_fused_kernel<<<blocks, threads>>>(qp, fc_w, fc_b,
                                          (const float4*)x, (float4*)d_out, nquad);
    (void)n_in; (void)in_sizes;
}

// round 8
// speedup vs baseline: 1.2989x; 1.2989x over previous
#include <cuda_runtime.h>

// ---------------------------------------------------------------------------
// QNNClassifier fused single-kernel, 2-tile pipelined main path.
//
//   ev = (1, cos x0, sin x0)^T K (1, cos x1, sin x1)
//
// K (9 coefficients, fc_w/fc_b folded) computed once per block by warp 0
// (shfl-parallel complex pipeline, hidden under the block's front-batched
// DRAM loads). Each thread handles 8 samples as two float4-tiles; all four
// input loads are issued before the barrier (MLP=4), so the K prologue and
// the DRAM latency of BOTH tiles overlap. 1024 blocks -> half the prologue
// count of the 4-sample/thread version.
// ---------------------------------------------------------------------------

struct Cx { float re, im; };
__device__ __forceinline__ Cx cmul(Cx a, Cx b) {
    return { a.re * b.re - a.im * b.im, a.re * b.im + a.im * b.re };
}

// Warp-collective (warp 0 only). Writes the 9 coefficients to sK.
__device__ __forceinline__ void warp_compute_K(const float* __restrict__ qp,
                                               const float* __restrict__ fc_w,
                                               const float* __restrict__ fc_b,
                                               float* sK) {
    const unsigned FULL = 0xffffffffu;
    int L = threadIdx.x & 31;
    int i = (L >> 2) & 3, j = L & 3;
    int a = (i >> 1) & 1, b = i & 1;

    float ur = (i == j) ? 1.f : 0.f, ui = 0.f;

    #pragma unroll
    for (int l = 0; l < 2; l++) {
        float ph0 = qp[l * 6 + 0], th0 = qp[l * 6 + 1], om0 = qp[l * 6 + 2];
        float ph1 = qp[l * 6 + 3], th1 = qp[l * 6 + 4], om1 = qp[l * 6 + 5];

        float s0, c0; __sincosf(0.5f * th0, &s0, &c0);
        float sp0, cp0, sm0, cm0;
        __sincosf(-0.5f * (ph0 + om0), &sp0, &cp0);   // ep0
        __sincosf( 0.5f * (ph0 - om0), &sm0, &cm0);   // em0
        Cx r0_00 = {  cp0 * c0,  sp0 * c0 };
        Cx r0_01 = { -cm0 * s0, -sm0 * s0 };
        Cx r0_10 = {  cm0 * s0, -sm0 * s0 };
        Cx r0_11 = {  cp0 * c0, -sp0 * c0 };

        float s1, c1; __sincosf(0.5f * th1, &s1, &c1);
        float sp1, cp1, sm1, cm1;
        __sincosf(-0.5f * (ph1 + om1), &sp1, &cp1);
        __sincosf( 0.5f * (ph1 - om1), &sm1, &cm1);
        Cx r1_00 = {  cp1 * c1,  sp1 * c1 };
        Cx r1_01 = { -cm1 * s1, -sm1 * s1 };
        Cx r1_10 = {  cm1 * s1, -sm1 * s1 };
        Cx r1_11 = {  cp1 * c1, -sp1 * c1 };

        Cx r0c0 = a ? r0_10 : r0_00;   // r0[a][0]
        Cx r0c1 = a ? r0_11 : r0_01;   // r0[a][1]
        Cx r1d0 = b ? r1_10 : r1_00;   // r1[b][0]
        Cx r1d1 = b ? r1_11 : r1_01;   // r1[b][1]

        // T[i][j] = sum_k kron(r0,r1)[i][k] * U[k][j]
        Cx T = { 0.f, 0.f };
        #pragma unroll
        for (int k = 0; k < 4; k++) {
            Cx g = cmul((k & 2) ? r0c1 : r0c0, (k & 1) ? r1d1 : r1d0);
            float wre = __shfl_sync(FULL, ur, 4 * k + j);
            float wim = __shfl_sync(FULL, ui, 4 * k + j);
            T.re += g.re * wre - g.im * wim;
            T.im += g.re * wim + g.im * wre;
        }
        // CNOT01 then CNOT10: row permutation new[i] = T[perm[i]], perm={0,2,3,1}
        int pi = (0x78 >> (2 * i)) & 3;
        ur = __shfl_sync(FULL, T.re, 4 * pi + j);
        ui = __shfl_sync(FULL, T.im, 4 * pi + j);
    }

    // A[i][j] = Re( sum_k z_k conj(U[k][i]) U[k][j] ), z=(1,1,-1,-1)
    float acc = 0.f;
    #pragma unroll
    for (int k = 0; k < 4; k++) {
        float ire = __shfl_sync(FULL, ur, 4 * k + i);
        float iim = __shfl_sync(FULL, ui, 4 * k + i);
        float jre = __shfl_sync(FULL, ur, 4 * k + j);
        float jim = __shfl_sync(FULL, ui, 4 * k + j);
        float dot = ire * jre + iim * jim;
        acc += (k < 2) ? dot : -dot;
    }

    float w = fc_w[0];
    float A00 = w * __shfl_sync(FULL, acc, 0);
    float A01 = w * __shfl_sync(FULL, acc, 1);
    float A02 = w * __shfl_sync(FULL, acc, 2);
    float A03 = w * __shfl_sync(FULL, acc, 3);
    float A11 = w * __shfl_sync(FULL, acc, 5);
    float A12 = w * __shfl_sync(FULL, acc, 6);
    float A13 = w * __shfl_sync(FULL, acc, 7);
    float A22 = w * __shfl_sync(FULL, acc, 10);
    float A23 = w * __shfl_sync(FULL, acc, 11);
    float A33 = w * __shfl_sync(FULL, acc, 15);

    if (L == 0) {
        sK[0] = 0.25f * (A00 + A11 + A22 + A33) + fc_b[0];
        sK[1] = 0.25f * (A00 - A11 + A22 - A33);   // C1
        sK[2] = 0.50f * (A01 + A23);               // S1
        sK[3] = 0.25f * (A00 + A11 - A22 - A33);   // C0
        sK[4] = 0.25f * (A00 - A11 - A22 + A33);   // C0C1
        sK[5] = 0.50f * (A01 - A23);               // C0S1
        sK[6] = 0.50f * (A02 + A13);               // S0
        sK[7] = 0.50f * (A02 - A13);               // S0C1
        sK[8] = 0.50f * (A03 + A12);               // S0S1
    }
}

__device__ __forceinline__ void eval_tile(const float k[9], const float4& xa,
                                          const float4& xb, float4& o) {
    float xs[8] = { xa.x, xa.y, xa.z, xa.w, xb.x, xb.y, xb.z, xb.w };
    float res[4];
    #pragma unroll
    for (int s = 0; s < 4; s++) {
        float C0, S0, C1, S1;
        __sincosf(xs[2 * s + 0], &S0, &C0);
        __sincosf(xs[2 * s + 1], &S1, &C1);
        float row0 = k[0] + k[1] * C1 + k[2] * S1;
        float row1 = k[3] + k[4] * C1 + k[5] * S1;
        float row2 = k[6] + k[7] * C1 + k[8] * S1;
        res[s] = row0 + C0 * row1 + S0 * row2;
    }
    o = make_float4(res[0], res[1], res[2], res[3]);
}

// 8 samples per thread: two tiles of (2 input float4 -> 1 output float4).
__global__ void __launch_bounds__(256)
qnn_fused_kernel(const float* __restrict__ qp,
                 const float* __restrict__ fc_w,
                 const float* __restrict__ fc_b,
                 const float4* __restrict__ x4,
                 float4* __restrict__ out4,
                 int half_quads) {   // = nquad/2
    __shared__ float sK[9];
    unsigned t = blockIdx.x * 256u + threadIdx.x;
    bool ok = t < (unsigned)half_quads;
    unsigned t2 = t + (unsigned)half_quads;

    // Front-batch ALL DRAM loads (MLP=4) before the K barrier.
    float4 xa0, xb0, xa1, xb1;
    if (ok) {
        xa0 = __ldcs(&x4[2u * t  + 0]);
        xb0 = __ldcs(&x4[2u * t  + 1]);
        xa1 = __ldcs(&x4[2u * t2 + 0]);
        xb1 = __ldcs(&x4[2u * t2 + 1]);
    }

    if (threadIdx.x < 32) {
        warp_compute_K(qp, fc_w, fc_b, sK);
    }
    __syncthreads();

    if (!ok) return;

    float k[9];
    #pragma unroll
    for (int m = 0; m < 9; m++) k[m] = sK[m];

    float4 o0, o1;
    eval_tile(k, xa0, xb0, o0);
    __stcs(&out4[t], o0);
    eval_tile(k, xa1, xb1, o1);
    __stcs(&out4[t2], o1);
}

extern "C" void kernel_launch(void* const* d_in, const int* in_sizes, int n_in,
                              void* d_out, int out_size) {
    const float* x    = (const float*)d_in[0];   // [B, 2]
    const float* qp   = (const float*)d_in[1];   // [2, 2, 3]
    const float* fc_w = (const float*)d_in[2];   // [1, 1]
    const float* fc_b = (const float*)d_in[3];   // [1]

    int nquad = out_size / 4;        // float4 outputs
    int half  = nquad / 2;           // two tiles per thread
    int threads = 256;
    int blocks = (half + threads - 1) / threads;   // 1024 for B=2M
    qnn_fused_kernel<<<blocks, threads>>>(qp, fc_w, fc_b,
                                          (const float4*)x, (float4*)d_out, half);
    (void)n_in; (void)in_sizes;
}